// round 14
// baseline (speedup 1.0000x reference)
#include <cuda_runtime.h>
#include <cuda_fp16.h>
#include <cstdint>

// Problem constants
#define S_LEN 2048
#define D_MODEL 4096
#define N_HEADS 32
#define N_KV 8
#define HEAD_DIM 128
#define KVDIM (N_KV * HEAD_DIM)   // 1024

#define QK_SCALE 0.08838834764831845f  // 1/sqrt(128)
#define QRANGE 16256.0f                // 127*128

// ---------------------------------------------------------------------------
// Scratch (device globals)
// ---------------------------------------------------------------------------
__device__ __align__(128) int8_t g_x1[S_LEN * D_MODEL];
__device__ __align__(128) int8_t g_x0[S_LEN * D_MODEL];
__device__ __align__(128) float  g_sx[S_LEN];
__device__ __align__(128) int8_t g_wq1[D_MODEL * D_MODEL];  // [N,K]
__device__ __align__(128) int8_t g_wq0[D_MODEL * D_MODEL];
__device__ __align__(128) float  g_swq[D_MODEL];
__device__ __align__(128) int8_t g_wk1[KVDIM * D_MODEL];
__device__ __align__(128) int8_t g_wk0[KVDIM * D_MODEL];
__device__ __align__(128) float  g_swk[KVDIM];
__device__ __align__(128) int8_t g_wv1[KVDIM * D_MODEL];
__device__ __align__(128) int8_t g_wv0[KVDIM * D_MODEL];
__device__ __align__(128) float  g_swv[KVDIM];
__device__ __align__(128) int8_t g_wo1[D_MODEL * D_MODEL];
__device__ __align__(128) int8_t g_wo0[D_MODEL * D_MODEL];
__device__ __align__(128) float  g_swo[D_MODEL];
__device__ __align__(128) float  g_aof[S_LEN * D_MODEL];
__device__ __align__(128) int8_t g_ao1[S_LEN * D_MODEL];
__device__ __align__(128) int8_t g_ao0[S_LEN * D_MODEL];
__device__ __align__(128) float  g_sao[S_LEN];
// flash inputs stay fp16 hi/lo
__device__ __align__(128) __half g_qh[S_LEN * D_MODEL];
__device__ __align__(128) __half g_ql[S_LEN * D_MODEL];
__device__ __align__(128) __half g_kh[S_LEN * KVDIM];
__device__ __align__(128) __half g_kl[S_LEN * KVDIM];
__device__ __align__(128) __half g_vh[S_LEN * KVDIM];
__device__ __align__(128) __half g_vl[S_LEN * KVDIM];

// ---------------------------------------------------------------------------
// Helpers
// ---------------------------------------------------------------------------
__device__ __forceinline__ uint32_t smem_u32(const void* p) {
    uint32_t a;
    asm("{ .reg .u64 t; cvta.to.shared.u64 t, %1; cvt.u32.u64 %0, t; }"
        : "=r"(a) : "l"(p));
    return a;
}
__device__ __forceinline__ uint32_t pack_h2f(float a, float b) {
    __half2 h = __floats2half2_rn(a, b);
    return *reinterpret_cast<uint32_t*>(&h);
}
__device__ __forceinline__ uint32_t pack_resid(uint32_t h, float a, float b) {
    __half2 hh = *reinterpret_cast<__half2*>(&h);
    float2 f = __half22float2(hh);
    return pack_h2f(a - f.x, b - f.y);
}
__device__ __forceinline__ float2 h2f2(uint32_t u) {
    __half2 hh = *reinterpret_cast<__half2*>(&u);
    return __half22float2(hh);
}

#define LDSM4(r0, r1, r2, r3, addr)                                           \
    asm volatile("ldmatrix.sync.aligned.m8n8.x4.shared.b16 {%0,%1,%2,%3}, [%4];" \
                 : "=r"(r0), "=r"(r1), "=r"(r2), "=r"(r3) : "r"(addr))
#define LDSM4T(r0, r1, r2, r3, addr)                                          \
    asm volatile("ldmatrix.sync.aligned.m8n8.x4.trans.shared.b16 {%0,%1,%2,%3}, [%4];" \
                 : "=r"(r0), "=r"(r1), "=r"(r2), "=r"(r3) : "r"(addr))
#define MMA16816(d, a, b)                                                     \
    asm volatile(                                                             \
        "mma.sync.aligned.m16n8k16.row.col.f32.f16.f16.f32 "                  \
        "{%0,%1,%2,%3}, {%4,%5,%6,%7}, {%8,%9}, {%0,%1,%2,%3};"               \
        : "+f"((d)[0]), "+f"((d)[1]), "+f"((d)[2]), "+f"((d)[3])              \
        : "r"((a)[0]), "r"((a)[1]), "r"((a)[2]), "r"((a)[3]),                 \
          "r"((b)[0]), "r"((b)[1]))
#define MMA16816H(d, a, b)                                                    \
    asm volatile(                                                             \
        "mma.sync.aligned.m16n8k16.row.col.f16.f16.f16.f16 "                  \
        "{%0,%1}, {%2,%3,%4,%5}, {%6,%7}, {%0,%1};"                           \
        : "+r"((d)[0]), "+r"((d)[1])                                          \
        : "r"((a)[0]), "r"((a)[1]), "r"((a)[2]), "r"((a)[3]),                 \
          "r"((b)[0]), "r"((b)[1]))
#define IMMA16832(d, a, b)                                                    \
    asm volatile(                                                             \
        "mma.sync.aligned.m16n8k32.row.col.s32.s8.s8.s32 "                    \
        "{%0,%1,%2,%3}, {%4,%5,%6,%7}, {%8,%9}, {%0,%1,%2,%3};"               \
        : "+r"((d)[0]), "+r"((d)[1]), "+r"((d)[2]), "+r"((d)[3])              \
        : "r"((a)[0]), "r"((a)[1]), "r"((a)[2]), "r"((a)[3]),                 \
          "r"((b)[0]), "r"((b)[1]))
#define CP16(s, g)                                                            \
    asm volatile("cp.async.cg.shared.global [%0], [%1], 16;"                  \
                 :: "r"(s), "l"(g) : "memory")

// ---------------------------------------------------------------------------
// int8 limb GEMM: C = sa[r]*sb[c]*(16384*A1B1 + 128*(A1B0+A0B1))
// 512 threads, 16 warps, 32x32 warp tiles, K-chunk 128 (4x k32 steps).
// Same smem byte layout as the fp16 version (byte-identical fragments).
// Epilogue modes: 0 = fp32 out, 1 = rope+scale+fp16 split, 2 = fp16 split.
// ---------------------------------------------------------------------------
#define G_ROWB 144
#define G_TILEB (128 * G_ROWB)
#define G_STAGE (4 * G_TILEB)
#define G_SMEM (2 * G_STAGE)

struct GemmArgs {
    const int8_t *A1, *A0, *B1, *B0;
    const float *sa, *sb;
    float* Cf;
    __half *Ch, *Cl;
    const float *fc, *fs;
    int N;
    float oscale;
    int mode;
};

__device__ __forceinline__ void gemm_body(const GemmArgs& ga, int m0, int n0,
                                          int K, char* smem) {
    const uint32_t sb_ = smem_u32(smem);
    const int tid = threadIdx.x;
    const int lane = tid & 31;
    const int wid = tid >> 5;
    const int wm = wid & 3;
    const int wn = wid >> 2;

    // Loader: K-chunk 128 bytes/row; 2 cp.async per tile per thread
    uint32_t s_off[2];
    size_t g_off[2];
#pragma unroll
    for (int it = 0; it < 2; it++) {
        int idx = it * 512 + tid;
        int r = idx >> 3;
        int c = idx & 7;
        s_off[it] = (uint32_t)(r * G_ROWB + c * 16);
        g_off[it] = (size_t)r * K + c * 16;
    }
    const int8_t* src[4] = {ga.A1 + (size_t)m0 * K, ga.A0 + (size_t)m0 * K,
                            ga.B1 + (size_t)n0 * K, ga.B0 + (size_t)n0 * K};

    auto issue = [&](int i) {
        const uint32_t sbase = sb_ + (i & 1) * G_STAGE;
        const int k0 = i << 7;
#pragma unroll
        for (int t4 = 0; t4 < 4; t4++) {
            const int8_t* g = src[t4] + k0;
            const uint32_t st = sbase + t4 * G_TILEB;
#pragma unroll
            for (int it = 0; it < 2; it++) CP16(st + s_off[it], g + g_off[it]);
        }
        asm volatile("cp.async.commit_group;" ::: "memory");
    };

    uint32_t aoff[2], boff[2];
#pragma unroll
    for (int mt = 0; mt < 2; mt++) {
        int row = wm * 32 + mt * 16 + (lane & 15);
        aoff[mt] = (uint32_t)(row * G_ROWB + (lane >> 4) * 16);
    }
#pragma unroll
    for (int ng = 0; ng < 2; ng++) {
        int row = wn * 32 + ng * 16 + (lane & 15);
        boff[ng] = (uint32_t)(2 * G_TILEB + row * G_ROWB + (lane >> 4) * 16);
    }

    int acc1[2][4][4], accX[2][4][4];
#pragma unroll
    for (int mt = 0; mt < 2; mt++)
#pragma unroll
        for (int n = 0; n < 4; n++)
#pragma unroll
            for (int e = 0; e < 4; e++) {
                acc1[mt][n][e] = 0;
                accX[mt][n][e] = 0;
            }

    const int niter = K >> 7;
    issue(0);

    for (int i = 0; i < niter; i++) {
        asm volatile("cp.async.wait_group 0;" ::: "memory");
        __syncthreads();
        if (i + 1 < niter) issue(i + 1);

        const uint32_t st = sb_ + (i & 1) * G_STAGE;
#pragma unroll
        for (int ks = 0; ks < 4; ks++) {
            const uint32_t kadd = ks * 32;
            uint32_t a1[2][4], a0[2][4], b1[4][2], b0[4][2];
#pragma unroll
            for (int mt = 0; mt < 2; mt++) {
                LDSM4(a1[mt][0], a1[mt][1], a1[mt][2], a1[mt][3],
                      st + aoff[mt] + kadd);
                LDSM4(a0[mt][0], a0[mt][1], a0[mt][2], a0[mt][3],
                      st + G_TILEB + aoff[mt] + kadd);
            }
#pragma unroll
            for (int ng = 0; ng < 2; ng++) {
                uint32_t r0, r1, r2, r3;
                LDSM4(r0, r1, r2, r3, st + boff[ng] + kadd);
                b1[ng * 2][0] = r0; b1[ng * 2][1] = r2;
                b1[ng * 2 + 1][0] = r1; b1[ng * 2 + 1][1] = r3;
                LDSM4(r0, r1, r2, r3, st + G_TILEB + boff[ng] + kadd);
                b0[ng * 2][0] = r0; b0[ng * 2][1] = r2;
                b0[ng * 2 + 1][0] = r1; b0[ng * 2 + 1][1] = r3;
            }
#pragma unroll
            for (int mt = 0; mt < 2; mt++)
#pragma unroll
                for (int n = 0; n < 4; n++) IMMA16832(acc1[mt][n], a1[mt], b1[n]);
#pragma unroll
            for (int mt = 0; mt < 2; mt++)
#pragma unroll
                for (int n = 0; n < 4; n++) IMMA16832(accX[mt][n], a1[mt], b0[n]);
#pragma unroll
            for (int mt = 0; mt < 2; mt++)
#pragma unroll
                for (int n = 0; n < 4; n++) IMMA16832(accX[mt][n], a0[mt], b1[n]);
        }
    }

    const int N = ga.N;
    const int row_b = m0 + wm * 32 + (lane >> 2);
    const int col_b = n0 + wn * 32 + (lane & 3) * 2;

#pragma unroll
    for (int mt = 0; mt < 2; mt++) {
        const int r0_ = row_b + mt * 16;
        const int r1_ = r0_ + 8;
        const float sa0 = ga.sa[r0_];
        const float sa1 = ga.sa[r1_];
#pragma unroll
        for (int n = 0; n < 4; n++) {
            const int col = col_b + n * 8;
            const float sb0 = ga.sb[col];
            const float sb1 = ga.sb[col + 1];
            float v0 = sa0 * sb0 *
                       ((float)acc1[mt][n][0] * 16384.f + (float)accX[mt][n][0] * 128.f);
            float v1 = sa0 * sb1 *
                       ((float)acc1[mt][n][1] * 16384.f + (float)accX[mt][n][1] * 128.f);
            float v2 = sa1 * sb0 *
                       ((float)acc1[mt][n][2] * 16384.f + (float)accX[mt][n][2] * 128.f);
            float v3 = sa1 * sb1 *
                       ((float)acc1[mt][n][3] * 16384.f + (float)accX[mt][n][3] * 128.f);
            if (ga.mode == 0) {
                float* c0 = ga.Cf + (size_t)r0_ * N + col;
                float* c1 = ga.Cf + (size_t)r1_ * N + col;
                c0[0] = v0; c0[1] = v1;
                c1[0] = v2; c1[1] = v3;
            } else {
                float x0 = v0, y0 = v1, x1 = v2, y1 = v3;
                if (ga.mode == 1) {
                    int p = (col & 127) >> 1;
                    float c0v = ga.fc[r0_ * 64 + p], s0v = ga.fs[r0_ * 64 + p];
                    float c1v = ga.fc[r1_ * 64 + p], s1v = ga.fs[r1_ * 64 + p];
                    float nx0 = (x0 * c0v - y0 * s0v) * ga.oscale;
                    float ny0 = (x0 * s0v + y0 * c0v) * ga.oscale;
                    float nx1 = (x1 * c1v - y1 * s1v) * ga.oscale;
                    float ny1 = (x1 * s1v + y1 * c1v) * ga.oscale;
                    x0 = nx0; y0 = ny0; x1 = nx1; y1 = ny1;
                }
                uint32_t h0 = pack_h2f(x0, y0), l0 = pack_resid(h0, x0, y0);
                uint32_t h1 = pack_h2f(x1, y1), l1 = pack_resid(h1, x1, y1);
                *(uint32_t*)(ga.Ch + (size_t)r0_ * N + col) = h0;
                *(uint32_t*)(ga.Cl + (size_t)r0_ * N + col) = l0;
                *(uint32_t*)(ga.Ch + (size_t)r1_ * N + col) = h1;
                *(uint32_t*)(ga.Cl + (size_t)r1_ * N + col) = l1;
            }
        }
    }
}

// Fused QKV projection
__global__ void __launch_bounds__(512, 1)
qkv_gemm(const int8_t* __restrict__ x1, const int8_t* __restrict__ x0,
         const float* __restrict__ sx,
         const float* __restrict__ fc, const float* __restrict__ fs,
         const int8_t* __restrict__ wq1, const int8_t* __restrict__ wq0,
         const float* __restrict__ swq,
         const int8_t* __restrict__ wk1, const int8_t* __restrict__ wk0,
         const float* __restrict__ swk,
         const int8_t* __restrict__ wv1, const int8_t* __restrict__ wv0,
         const float* __restrict__ swv,
         __half* __restrict__ qh, __half* __restrict__ ql,
         __half* __restrict__ kh, __half* __restrict__ kl,
         __half* __restrict__ vh, __half* __restrict__ vl) {
    extern __shared__ char smem[];
    const int bx = blockIdx.x;
    GemmArgs ga;
    ga.A1 = x1; ga.A0 = x0; ga.sa = sx;
    ga.fc = fc; ga.fs = fs;
    ga.Cf = nullptr;
    int n0;
    if (bx < 32) {
        ga.B1 = wq1; ga.B0 = wq0; ga.sb = swq; ga.Ch = qh; ga.Cl = ql;
        ga.N = D_MODEL; ga.mode = 1; ga.oscale = QK_SCALE;
        n0 = bx * 128;
    } else if (bx < 40) {
        ga.B1 = wk1; ga.B0 = wk0; ga.sb = swk; ga.Ch = kh; ga.Cl = kl;
        ga.N = KVDIM; ga.mode = 1; ga.oscale = 1.0f;
        n0 = (bx - 32) * 128;
    } else {
        ga.B1 = wv1; ga.B0 = wv0; ga.sb = swv; ga.Ch = vh; ga.Cl = vl;
        ga.N = KVDIM; ga.mode = 2; ga.oscale = 1.0f;
        n0 = (bx - 40) * 128;
    }
    gemm_body(ga, blockIdx.y * 128, n0, D_MODEL, smem);
}

__global__ void __launch_bounds__(512, 1)
wo_gemm(const int8_t* __restrict__ ao1, const int8_t* __restrict__ ao0,
        const float* __restrict__ sao,
        const int8_t* __restrict__ wo1, const int8_t* __restrict__ wo0,
        const float* __restrict__ swo, float* __restrict__ out) {
    extern __shared__ char smem[];
    GemmArgs ga;
    ga.A1 = ao1; ga.A0 = ao0; ga.sa = sao;
    ga.B1 = wo1; ga.B0 = wo0; ga.sb = swo;
    ga.Cf = out; ga.Ch = nullptr; ga.Cl = nullptr;
    ga.fc = nullptr; ga.fs = nullptr;
    ga.N = D_MODEL; ga.oscale = 1.0f; ga.mode = 0;
    gemm_body(ga, blockIdx.y * 128, blockIdx.x * 128, D_MODEL, smem);
}

// ---------------------------------------------------------------------------
// Quantization kernels
// ---------------------------------------------------------------------------
// Per-row 2-limb int8 quantization: in[M,K] fp32 -> q1,q0, scale srow.
__global__ void __launch_bounds__(256) rowquant(const float* __restrict__ in,
                                                int8_t* __restrict__ q1,
                                                int8_t* __restrict__ q0,
                                                float* __restrict__ srow, int K) {
    __shared__ float red[256];
    const int row = blockIdx.x;
    const int tid = threadIdx.x;
    const float* base = in + (size_t)row * K;
    float m = 0.f;
    for (int i = tid; i < K; i += 256) m = fmaxf(m, fabsf(base[i]));
    red[tid] = m;
    __syncthreads();
#pragma unroll
    for (int s = 128; s > 0; s >>= 1) {
        if (tid < s) red[tid] = fmaxf(red[tid], red[tid + s]);
        __syncthreads();
    }
    const float mx = fmaxf(red[0], 1e-30f);
    const float inv = QRANGE / mx;
    if (tid == 0) srow[row] = mx / QRANGE;
    int8_t* o1 = q1 + (size_t)row * K;
    int8_t* o0 = q0 + (size_t)row * K;
    for (int i = tid; i < K; i += 256) {
        float v = base[i] * inv;
        float f1 = rintf(v * 0.0078125f);
        float f0 = rintf(v - 128.f * f1);
        o1[i] = (int8_t)(int)f1;
        o0[i] = (int8_t)(int)f0;
    }
}

// Column max for W[K,N] -> scale[n]; z selects weight.
__global__ void colmax_all(const float* __restrict__ wq,
                           const float* __restrict__ wk,
                           const float* __restrict__ wv,
                           const float* __restrict__ wo,
                           float* __restrict__ sq, float* __restrict__ sk,
                           float* __restrict__ sv, float* __restrict__ so) {
    const int z = blockIdx.z;
    const float* W;
    float* s;
    int N;
    if (z == 0)      { W = wq; s = sq; N = D_MODEL; }
    else if (z == 1) { W = wk; s = sk; N = KVDIM; }
    else if (z == 2) { W = wv; s = sv; N = KVDIM; }
    else             { W = wo; s = so; N = D_MODEL; }
    const int n = blockIdx.x * blockDim.x + threadIdx.x;
    if (n >= N) return;
    float m = 0.f;
    for (int k = 0; k < D_MODEL; k++) m = fmaxf(m, fabsf(W[(size_t)k * N + n]));
    s[n] = fmaxf(m, 1e-30f) / QRANGE;
}

// Transpose + quantize: W[K,N] -> q1,q0 [N,K]; z selects weight.
__global__ void __launch_bounds__(256) transpose_quant_all(
    const float* __restrict__ wq, const float* __restrict__ wk,
    const float* __restrict__ wv, const float* __restrict__ wo,
    const float* __restrict__ sq, const float* __restrict__ sk,
    const float* __restrict__ sv, const float* __restrict__ so,
    int8_t* __restrict__ wq1, int8_t* __restrict__ wq0,
    int8_t* __restrict__ wk1, int8_t* __restrict__ wk0,
    int8_t* __restrict__ wv1, int8_t* __restrict__ wv0,
    int8_t* __restrict__ wo1, int8_t* __restrict__ wo0) {
    const int z = blockIdx.z;
    const float* W;
    const float* sN;
    int8_t *q1, *q0;
    int N;
    if (z == 0)      { W = wq; sN = sq; q1 = wq1; q0 = wq0; N = D_MODEL; }
    else if (z == 1) { W = wk; sN = sk; q1 = wk1; q0 = wk0; N = KVDIM; }
    else if (z == 2) { W = wv; sN = sv; q1 = wv1; q0 = wv0; N = KVDIM; }
    else             { W = wo; sN = so; q1 = wo1; q0 = wo0; N = D_MODEL; }
    const int n0 = blockIdx.x * 32;
    if (n0 >= N) return;
    const int k0 = blockIdx.y * 32;
    const int K = D_MODEL;

    __shared__ float t[32][33];
    const int tx = threadIdx.x;
#pragma unroll
    for (int j = threadIdx.y; j < 32; j += 8)
        t[j][tx] = W[(size_t)(k0 + j) * N + n0 + tx];
    __syncthreads();
#pragma unroll
    for (int j = threadIdx.y; j < 32; j += 8) {
        float inv = 1.0f / sN[n0 + j];
        float v = t[tx][j] * inv;
        float f1 = rintf(v * 0.0078125f);
        float f0 = rintf(v - 128.f * f1);
        size_t o = (size_t)(n0 + j) * K + k0 + tx;
        q1[o] = (int8_t)(int)f1;
        q0[o] = (int8_t)(int)f0;
    }
}

// ---------------------------------------------------------------------------
// HMMA flash attention (fp16 hi/lo), writes fp32 O.
// ---------------------------------------------------------------------------
#define FRSB 272
#define FQ_BYTES (128 * FRSB)
#define FKV_TILE (64 * FRSB)
#define FSTAGE (4 * FKV_TILE)
#define FSMEM (2 * FQ_BYTES + 2 * FSTAGE)

__global__ void __launch_bounds__(256, 1)
flash_hmma(const __half* __restrict__ Qh, const __half* __restrict__ Ql,
           const __half* __restrict__ Kh, const __half* __restrict__ Kl,
           const __half* __restrict__ Vh, const __half* __restrict__ Vl,
           float* __restrict__ O) {
    extern __shared__ char smf[];
    const uint32_t sb = smem_u32(smf);
    const int tid = threadIdx.x, lane = tid & 31, w = tid >> 5;
    const int head = blockIdx.y, kvh = head >> 2;
    const int qt = gridDim.x - 1 - blockIdx.x;
    const int q0 = qt * 128;
    const int nt = (q0 >> 6) + 2;

#pragma unroll
    for (int it = 0; it < 8; it++) {
        int idx = it * 256 + tid;
        int r = idx >> 4, c = idx & 15;
        size_t go = (size_t)(q0 + r) * D_MODEL + head * HEAD_DIM + c * 8;
        uint32_t so = (uint32_t)(r * FRSB + c * 16);
        CP16(sb + so, Qh + go);
        CP16(sb + FQ_BYTES + so, Ql + go);
    }

    const __half* kvsrc[4] = {Kh, Kl, Vh, Vl};
    auto issue_kv = [&](int t) {
        const int k0 = t << 6;
        const uint32_t stage = sb + 2 * FQ_BYTES + (t & 1) * FSTAGE;
#pragma unroll
        for (int it = 0; it < 16; it++) {
            int idx = it * 256 + tid;
            int op = idx >> 10;
            int r = (idx >> 4) & 63, c = idx & 15;
            const __half* g = kvsrc[op] + (size_t)(k0 + r) * KVDIM +
                              kvh * HEAD_DIM + c * 8;
            CP16(stage + op * FKV_TILE + r * FRSB + c * 16, g);
        }
        asm volatile("cp.async.commit_group;" ::: "memory");
    };
    issue_kv(0);

    const uint32_t qa_h = sb + (w * 16 + (lane & 15)) * FRSB + (lane >> 4) * 16;
    const uint32_t qa_l = qa_h + FQ_BYTES;
    const uint32_t kvoff = (uint32_t)((lane & 15) * FRSB + (lane >> 4) * 16);

    float m_lo = -1e30f, m_hi = -1e30f, l_lo = 0.f, l_hi = 0.f;
    float o_acc[16][4];
#pragma unroll
    for (int nf = 0; nf < 16; nf++)
#pragma unroll
        for (int e = 0; e < 4; e++) o_acc[nf][e] = 0.f;

    const int row_lo_g = q0 + w * 16 + (lane >> 2);
    const int row_hi_g = row_lo_g + 8;

    for (int t = 0; t < nt; t++) {
        asm volatile("cp.async.wait_group 0;" ::: "memory");
        __syncthreads();
        if (t + 1 < nt) issue_kv(t + 1);

        const uint32_t stage = sb + 2 * FQ_BYTES + (t & 1) * FSTAGE;
        const uint32_t kb = stage + kvoff;
        const uint32_t kbl = kb + FKV_TILE;
        const uint32_t vb = stage + 2 * FKV_TILE + kvoff;
        const uint32_t vbl = vb + FKV_TILE;
        const int k0 = t << 6;

        float sa32[8][4];
        uint32_t sa16[8][2];
#pragma unroll
        for (int nf = 0; nf < 8; nf++) {
#pragma unroll
            for (int e = 0; e < 4; e++) sa32[nf][e] = 0.f;
            sa16[nf][0] = 0u;
            sa16[nf][1] = 0u;
        }

#pragma unroll
        for (int ks = 0; ks < 8; ks++) {
            uint32_t ah[4], al[4];
            LDSM4(ah[0], ah[1], ah[2], ah[3], qa_h + ks * 32);
            LDSM4(al[0], al[1], al[2], al[3], qa_l + ks * 32);
#pragma unroll
            for (int ng = 0; ng < 4; ng++) {
                uint32_t h0, h1, h2, h3, l0, l1, l2, l3;
                LDSM4(h0, h1, h2, h3, kb + ng * (16 * FRSB) + ks * 32);
                LDSM4(l0, l1, l2, l3, kbl + ng * (16 * FRSB) + ks * 32);
                uint32_t bh0[2] = {h0, h2}, bh1[2] = {h1, h3};
                uint32_t bl0[2] = {l0, l2}, bl1[2] = {l1, l3};
                MMA16816(sa32[2 * ng], ah, bh0);
                MMA16816H(sa16[2 * ng], al, bh0);
                MMA16816H(sa16[2 * ng], ah, bl0);
                MMA16816(sa32[2 * ng + 1], ah, bh1);
                MMA16816H(sa16[2 * ng + 1], al, bh1);
                MMA16816H(sa16[2 * ng + 1], ah, bl1);
            }
        }

        float sa[8][4];
#pragma unroll
        for (int nf = 0; nf < 8; nf++) {
            float2 rlo = h2f2(sa16[nf][0]);
            float2 rhi = h2f2(sa16[nf][1]);
            sa[nf][0] = sa32[nf][0] + rlo.x;
            sa[nf][1] = sa32[nf][1] + rlo.y;
            sa[nf][2] = sa32[nf][2] + rhi.x;
            sa[nf][3] = sa32[nf][3] + rhi.y;
        }

        if (t >= nt - 2) {
#pragma unroll
            for (int nf = 0; nf < 8; nf++) {
                int cb = k0 + nf * 8 + (lane & 3) * 2;
                if (cb > row_lo_g) sa[nf][0] = -1e30f;
                if (cb + 1 > row_lo_g) sa[nf][1] = -1e30f;
                if (cb > row_hi_g) sa[nf][2] = -1e30f;
                if (cb + 1 > row_hi_g) sa[nf][3] = -1e30f;
            }
        }

        float tm_lo = -1e30f, tm_hi = -1e30f;
#pragma unroll
        for (int nf = 0; nf < 8; nf++) {
            tm_lo = fmaxf(tm_lo, fmaxf(sa[nf][0], sa[nf][1]));
            tm_hi = fmaxf(tm_hi, fmaxf(sa[nf][2], sa[nf][3]));
        }
        tm_lo = fmaxf(tm_lo, __shfl_xor_sync(0xffffffffu, tm_lo, 1));
        tm_lo = fmaxf(tm_lo, __shfl_xor_sync(0xffffffffu, tm_lo, 2));
        tm_hi = fmaxf(tm_hi, __shfl_xor_sync(0xffffffffu, tm_hi, 1));
        tm_hi = fmaxf(tm_hi, __shfl_xor_sync(0xffffffffu, tm_hi, 2));

        float mn_lo = fmaxf(m_lo, tm_lo), mn_hi = fmaxf(m_hi, tm_hi);
        float al_lo = __expf(m_lo - mn_lo), al_hi = __expf(m_hi - mn_hi);
        m_lo = mn_lo; m_hi = mn_hi;

        float sum_lo = 0.f, sum_hi = 0.f;
#pragma unroll
        for (int nf = 0; nf < 8; nf++) {
            sa[nf][0] = __expf(sa[nf][0] - mn_lo);
            sa[nf][1] = __expf(sa[nf][1] - mn_lo);
            sa[nf][2] = __expf(sa[nf][2] - mn_hi);
            sa[nf][3] = __expf(sa[nf][3] - mn_hi);
            sum_lo += sa[nf][0] + sa[nf][1];
            sum_hi += sa[nf][2] + sa[nf][3];
        }
        sum_lo += __shfl_xor_sync(0xffffffffu, sum_lo, 1);
        sum_lo += __shfl_xor_sync(0xffffffffu, sum_lo, 2);
        sum_hi += __shfl_xor_sync(0xffffffffu, sum_hi, 1);
        sum_hi += __shfl_xor_sync(0xffffffffu, sum_hi, 2);
        l_lo = l_lo * al_lo + sum_lo;
        l_hi = l_hi * al_hi + sum_hi;

#pragma unroll
        for (int nf = 0; nf < 16; nf++) {
            o_acc[nf][0] *= al_lo; o_acc[nf][1] *= al_lo;
            o_acc[nf][2] *= al_hi; o_acc[nf][3] *= al_hi;
        }

        uint32_t pah[4][4], pal[4][4];
#pragma unroll
        for (int j = 0; j < 4; j++) {
            pah[j][0] = pack_h2f(sa[2 * j][0], sa[2 * j][1]);
            pal[j][0] = pack_resid(pah[j][0], sa[2 * j][0], sa[2 * j][1]);
            pah[j][1] = pack_h2f(sa[2 * j][2], sa[2 * j][3]);
            pal[j][1] = pack_resid(pah[j][1], sa[2 * j][2], sa[2 * j][3]);
            pah[j][2] = pack_h2f(sa[2 * j + 1][0], sa[2 * j + 1][1]);
            pal[j][2] = pack_resid(pah[j][2], sa[2 * j + 1][0], sa[2 * j + 1][1]);
            pah[j][3] = pack_h2f(sa[2 * j + 1][2], sa[2 * j + 1][3]);
            pal[j][3] = pack_resid(pah[j][3], sa[2 * j + 1][2], sa[2 * j + 1][3]);
        }

        uint32_t o16[16][2];
#pragma unroll
        for (int nf = 0; nf < 16; nf++) { o16[nf][0] = 0u; o16[nf][1] = 0u; }

#pragma unroll
        for (int j = 0; j < 4; j++) {
#pragma unroll
            for (int dg = 0; dg < 8; dg++) {
                uint32_t h0, h1, h2, h3, l0, l1, l2, l3;
                LDSM4T(h0, h1, h2, h3, vb + j * (16 * FRSB) + dg * 32);
                LDSM4T(l0, l1, l2, l3, vbl + j * (16 * FRSB) + dg * 32);
                uint32_t bh0[2] = {h0, h1}, bh1[2] = {h2, h3};
                uint32_t bl0[2] = {l0, l1}, bl1[2] = {l2, l3};
                MMA16816(o_acc[2 * dg], pah[j], bh0);
                MMA16816H(o16[2 * dg], pal[j], bh0);
                MMA16816H(o16[2 * dg], pah[j], bl0);
                MMA16816(o_acc[2 * dg + 1], pah[j], bh1);
                MMA16816H(o16[2 * dg + 1], pal[j], bh1);
                MMA16816H(o16[2 * dg + 1], pah[j], bl1);
            }
        }
#pragma unroll
        for (int nf = 0; nf < 16; nf++) {
            float2 rlo = h2f2(o16[nf][0]);
            float2 rhi = h2f2(o16[nf][1]);
            o_acc[nf][0] += rlo.x;
            o_acc[nf][1] += rlo.y;
            o_acc[nf][2] += rhi.x;
            o_acc[nf][3] += rhi.y;
        }
    }

    const float inv_lo = 1.f / l_lo, inv_hi = 1.f / l_hi;
#pragma unroll
    for (int nf = 0; nf < 16; nf++) {
        int col = head * HEAD_DIM + nf * 8 + (lane & 3) * 2;
        *(float2*)(O + (size_t)row_lo_g * D_MODEL + col) =
            make_float2(o_acc[nf][0] * inv_lo, o_acc[nf][1] * inv_lo);
        *(float2*)(O + (size_t)row_hi_g * D_MODEL + col) =
            make_float2(o_acc[nf][2] * inv_hi, o_acc[nf][3] * inv_hi);
    }
}

// ---------------------------------------------------------------------------
// Launch
// ---------------------------------------------------------------------------
extern "C" void kernel_launch(void* const* d_in, const int* in_sizes, int n_in,
                              void* d_out, int out_size) {
    const float* x  = (const float*)d_in[0];
    const float* fc = (const float*)d_in[1];
    const float* fs = (const float*)d_in[2];
    const float* wq = (const float*)d_in[4];
    const float* wk = (const float*)d_in[5];
    const float* wv = (const float*)d_in[6];
    const float* wo = (const float*)d_in[7];
    float* out = (float*)d_out;

    int8_t *x1, *x0, *wq1, *wq0, *wk1, *wk0, *wv1, *wv0, *wo1, *wo0, *ao1, *ao0;
    float *sx, *swq, *swk, *swv, *swo, *sao, *aof;
    __half *qh, *ql, *kh, *kl, *vh, *vl;
    cudaGetSymbolAddress((void**)&x1,  g_x1);
    cudaGetSymbolAddress((void**)&x0,  g_x0);
    cudaGetSymbolAddress((void**)&sx,  g_sx);
    cudaGetSymbolAddress((void**)&wq1, g_wq1);
    cudaGetSymbolAddress((void**)&wq0, g_wq0);
    cudaGetSymbolAddress((void**)&swq, g_swq);
    cudaGetSymbolAddress((void**)&wk1, g_wk1);
    cudaGetSymbolAddress((void**)&wk0, g_wk0);
    cudaGetSymbolAddress((void**)&swk, g_swk);
    cudaGetSymbolAddress((void**)&wv1, g_wv1);
    cudaGetSymbolAddress((void**)&wv0, g_wv0);
    cudaGetSymbolAddress((void**)&swv, g_swv);
    cudaGetSymbolAddress((void**)&wo1, g_wo1);
    cudaGetSymbolAddress((void**)&wo0, g_wo0);
    cudaGetSymbolAddress((void**)&swo, g_swo);
    cudaGetSymbolAddress((void**)&ao1, g_ao1);
    cudaGetSymbolAddress((void**)&ao0, g_ao0);
    cudaGetSymbolAddress((void**)&sao, g_sao);
    cudaGetSymbolAddress((void**)&aof, g_aof);
    cudaGetSymbolAddress((void**)&qh,  g_qh);
    cudaGetSymbolAddress((void**)&ql,  g_ql);
    cudaGetSymbolAddress((void**)&kh,  g_kh);
    cudaGetSymbolAddress((void**)&kl,  g_kl);
    cudaGetSymbolAddress((void**)&vh,  g_vh);
    cudaGetSymbolAddress((void**)&vl,  g_vl);

    cudaFuncSetAttribute(qkv_gemm, cudaFuncAttributeMaxDynamicSharedMemorySize, G_SMEM);
    cudaFuncSetAttribute(wo_gemm,  cudaFuncAttributeMaxDynamicSharedMemorySize, G_SMEM);
    cudaFuncSetAttribute(flash_hmma, cudaFuncAttributeMaxDynamicSharedMemorySize, FSMEM);

    // Quantize x and weights
    rowquant<<<S_LEN, 256>>>(x, x1, x0, sx, D_MODEL);
    colmax_all<<<dim3(D_MODEL / 256, 1, 4), 256>>>(wq, wk, wv, wo, swq, swk, swv, swo);
    transpose_quant_all<<<dim3(D_MODEL / 32, D_MODEL / 32, 4), dim3(32, 8)>>>(
        wq, wk, wv, wo, swq, swk, swv, swo,
        wq1, wq0, wk1, wk0, wv1, wv0, wo1, wo0);

    // QKV projections (int8 IMMA), fused rope/split epilogues
    qkv_gemm<<<dim3(48, S_LEN / 128), 512, G_SMEM>>>(
        x1, x0, sx, fc, fs, wq1, wq0, swq, wk1, wk0, swk, wv1, wv0, swv,
        qh, ql, kh, kl, vh, vl);

    // Flash attention (fp16 split), fp32 output
    flash_hmma<<<dim3(S_LEN / 128, N_HEADS), 256, FSMEM>>>(
        qh, ql, kh, kl, vh, vl, aof);

    // Quantize attention output, then WO projection (int8 IMMA)
    rowquant<<<S_LEN, 256>>>(aof, ao1, ao0, sao, D_MODEL);
    wo_gemm<<<dim3(D_MODEL / 128, S_LEN / 128), 512, G_SMEM>>>(
        ao1, ao0, sao, wo1, wo0, swo, out);
}

// round 16
// speedup vs baseline: 2.8681x; 2.8681x over previous
#include <cuda_runtime.h>
#include <cuda_fp16.h>
#include <cstdint>

// Problem constants
#define S_LEN 2048
#define D_MODEL 4096
#define N_HEADS 32
#define N_KV 8
#define HEAD_DIM 128
#define KVDIM (N_KV * HEAD_DIM)   // 1024

#define WSCALE 64.0f
#define INV_WSCALE (1.0f / 64.0f)
#define QK_SCALE 0.08838834764831845f  // 1/sqrt(128)

// ---------------------------------------------------------------------------
// Scratch (device globals)
// ---------------------------------------------------------------------------
__device__ __align__(128) __half g_xh[S_LEN * D_MODEL];
__device__ __align__(128) __half g_xl[S_LEN * D_MODEL];
__device__ __align__(128) __half g_qh[S_LEN * D_MODEL];
__device__ __align__(128) __half g_ql[S_LEN * D_MODEL];
__device__ __align__(128) __half g_kh[S_LEN * KVDIM];
__device__ __align__(128) __half g_kl[S_LEN * KVDIM];
__device__ __align__(128) __half g_vh[S_LEN * KVDIM];
__device__ __align__(128) __half g_vl[S_LEN * KVDIM];
__device__ __align__(128) __half g_aoh[S_LEN * D_MODEL];
__device__ __align__(128) __half g_aol[S_LEN * D_MODEL];
__device__ __align__(128) __half g_wq[D_MODEL * D_MODEL];  // [N,K], x64, fp16
__device__ __align__(128) __half g_wk[KVDIM * D_MODEL];
__device__ __align__(128) __half g_wv[KVDIM * D_MODEL];
__device__ __align__(128) __half g_wo[D_MODEL * D_MODEL];

// ---------------------------------------------------------------------------
// Helpers
// ---------------------------------------------------------------------------
__device__ __forceinline__ uint32_t smem_u32(const void* p) {
    uint32_t a;
    asm("{ .reg .u64 t; cvta.to.shared.u64 t, %1; cvt.u32.u64 %0, t; }"
        : "=r"(a) : "l"(p));
    return a;
}
__device__ __forceinline__ uint32_t pack_h2f(float a, float b) {
    __half2 h = __floats2half2_rn(a, b);
    return *reinterpret_cast<uint32_t*>(&h);
}
__device__ __forceinline__ uint32_t pack_resid(uint32_t h, float a, float b) {
    __half2 hh = *reinterpret_cast<__half2*>(&h);
    float2 f = __half22float2(hh);
    return pack_h2f(a - f.x, b - f.y);
}
__device__ __forceinline__ float2 h2f2(uint32_t u) {
    __half2 hh = *reinterpret_cast<__half2*>(&u);
    return __half22float2(hh);
}

#define LDSM4(r0, r1, r2, r3, addr)                                           \
    asm volatile("ldmatrix.sync.aligned.m8n8.x4.shared.b16 {%0,%1,%2,%3}, [%4];" \
                 : "=r"(r0), "=r"(r1), "=r"(r2), "=r"(r3) : "r"(addr))
#define LDSM4T(r0, r1, r2, r3, addr)                                          \
    asm volatile("ldmatrix.sync.aligned.m8n8.x4.trans.shared.b16 {%0,%1,%2,%3}, [%4];" \
                 : "=r"(r0), "=r"(r1), "=r"(r2), "=r"(r3) : "r"(addr))
#define MMA16816(d, a, b)                                                     \
    asm volatile(                                                             \
        "mma.sync.aligned.m16n8k16.row.col.f32.f16.f16.f32 "                  \
        "{%0,%1,%2,%3}, {%4,%5,%6,%7}, {%8,%9}, {%0,%1,%2,%3};"               \
        : "+f"((d)[0]), "+f"((d)[1]), "+f"((d)[2]), "+f"((d)[3])              \
        : "r"((a)[0]), "r"((a)[1]), "r"((a)[2]), "r"((a)[3]),                 \
          "r"((b)[0]), "r"((b)[1]))
#define MMA16816H(d, a, b)                                                    \
    asm volatile(                                                             \
        "mma.sync.aligned.m16n8k16.row.col.f16.f16.f16.f16 "                  \
        "{%0,%1}, {%2,%3,%4,%5}, {%6,%7}, {%0,%1};"                           \
        : "+r"((d)[0]), "+r"((d)[1])                                          \
        : "r"((a)[0]), "r"((a)[1]), "r"((a)[2]), "r"((a)[3]),                 \
          "r"((b)[0]), "r"((b)[1]))
#define CP16(s, g)                                                            \
    asm volatile("cp.async.cg.shared.global [%0], [%1], 16;"                  \
                 :: "r"(s), "l"(g) : "memory")

// ---------------------------------------------------------------------------
// 2-pass HMMA GEMM: C ~= cscale*(Ah + Al) @ B^T   (B single fp16 limb, x64)
// 512 threads, 16 warps, 32x32 warp tiles, K-chunk 64.
// Epilogue modes: 0 = fp32 out, 1 = rope+scale+split out, 2 = split out.
// ---------------------------------------------------------------------------
#define G_ROWB 144
#define G_TILEB (128 * G_ROWB)          // 18432
#define G_STAGE (3 * G_TILEB)           // 55296 (Ah, Al, B)
#define G_SMEM (2 * G_STAGE)            // 110592

struct GemmArgs {
    const __half *Ah, *Al, *B;
    float* Cf;
    __half *Ch, *Cl;
    const float *fc, *fs;
    int N;
    float cscale, oscale;
    int mode;
};

__device__ __forceinline__ void gemm_body(const GemmArgs& ga, int m0, int n0,
                                          int K, char* smem) {
    const uint32_t sb = smem_u32(smem);
    const int tid = threadIdx.x;
    const int lane = tid & 31;
    const int wid = tid >> 5;
    const int wm = wid & 3;
    const int wn = wid >> 2;

    uint32_t s_off[2];
    size_t g_off[2];
#pragma unroll
    for (int it = 0; it < 2; it++) {
        int idx = it * 512 + tid;
        int r = idx >> 3;
        int c = idx & 7;
        s_off[it] = (uint32_t)(r * G_ROWB + c * 16);
        g_off[it] = (size_t)r * K + c * 8;
    }
    const __half* src[3] = {ga.Ah + (size_t)m0 * K, ga.Al + (size_t)m0 * K,
                            ga.B + (size_t)n0 * K};

    auto issue = [&](int i) {
        const uint32_t sbase = sb + (i & 1) * G_STAGE;
        const int k0 = i << 6;
#pragma unroll
        for (int t3 = 0; t3 < 3; t3++) {
            const __half* g = src[t3] + k0;
            const uint32_t st = sbase + t3 * G_TILEB;
#pragma unroll
            for (int it = 0; it < 2; it++) CP16(st + s_off[it], g + g_off[it]);
        }
        asm volatile("cp.async.commit_group;" ::: "memory");
    };

    uint32_t aoff[2], boff[2];
#pragma unroll
    for (int mt = 0; mt < 2; mt++) {
        int row = wm * 32 + mt * 16 + (lane & 15);
        aoff[mt] = (uint32_t)(row * G_ROWB + (lane >> 4) * 16);
    }
#pragma unroll
    for (int ng = 0; ng < 2; ng++) {
        int row = wn * 32 + ng * 16 + (lane & 15);
        boff[ng] = (uint32_t)(2 * G_TILEB + row * G_ROWB + (lane >> 4) * 16);
    }

    float acc[2][4][4];
    uint32_t acc16[2][4][2];
#pragma unroll
    for (int mt = 0; mt < 2; mt++)
#pragma unroll
        for (int n = 0; n < 4; n++) {
#pragma unroll
            for (int e = 0; e < 4; e++) acc[mt][n][e] = 0.f;
            acc16[mt][n][0] = 0u;
            acc16[mt][n][1] = 0u;
        }

    const int niter = K >> 6;
    issue(0);

    for (int i = 0; i < niter; i++) {
        asm volatile("cp.async.wait_group 0;" ::: "memory");
        __syncthreads();
        if (i + 1 < niter) issue(i + 1);

        const uint32_t st = sb + (i & 1) * G_STAGE;
#pragma unroll
        for (int ks = 0; ks < 4; ks++) {
            const uint32_t kadd = ks * 32;
            uint32_t ah[2][4], al[2][4], bh[4][2];
#pragma unroll
            for (int mt = 0; mt < 2; mt++) {
                LDSM4(ah[mt][0], ah[mt][1], ah[mt][2], ah[mt][3],
                      st + aoff[mt] + kadd);
                LDSM4(al[mt][0], al[mt][1], al[mt][2], al[mt][3],
                      st + G_TILEB + aoff[mt] + kadd);
            }
#pragma unroll
            for (int ng = 0; ng < 2; ng++) {
                uint32_t r0, r1, r2, r3;
                LDSM4(r0, r1, r2, r3, st + boff[ng] + kadd);
                bh[ng * 2][0] = r0; bh[ng * 2][1] = r2;
                bh[ng * 2 + 1][0] = r1; bh[ng * 2 + 1][1] = r3;
            }
#pragma unroll
            for (int mt = 0; mt < 2; mt++)
#pragma unroll
                for (int n = 0; n < 4; n++) MMA16816(acc[mt][n], ah[mt], bh[n]);
#pragma unroll
            for (int mt = 0; mt < 2; mt++)
#pragma unroll
                for (int n = 0; n < 4; n++) MMA16816H(acc16[mt][n], al[mt], bh[n]);
        }
    }

    const int N = ga.N;
    const int row_b = m0 + wm * 32 + (lane >> 2);
    const int col_b = n0 + wn * 32 + (lane & 3) * 2;

#pragma unroll
    for (int mt = 0; mt < 2; mt++)
#pragma unroll
        for (int n = 0; n < 4; n++) {
            const int col = col_b + n * 8;
            const int r0_ = row_b + mt * 16;
            const int r1_ = r0_ + 8;
            float2 rlo = h2f2(acc16[mt][n][0]);
            float2 rhi = h2f2(acc16[mt][n][1]);
            float v0 = acc[mt][n][0] + rlo.x;
            float v1 = acc[mt][n][1] + rlo.y;
            float v2 = acc[mt][n][2] + rhi.x;
            float v3 = acc[mt][n][3] + rhi.y;
            if (ga.mode == 0) {
                float* c0 = ga.Cf + (size_t)r0_ * N + col;
                float* c1 = ga.Cf + (size_t)r1_ * N + col;
                c0[0] = v0 * ga.cscale;
                c0[1] = v1 * ga.cscale;
                c1[0] = v2 * ga.cscale;
                c1[1] = v3 * ga.cscale;
            } else {
                float x0 = v0 * ga.cscale, y0 = v1 * ga.cscale;
                float x1 = v2 * ga.cscale, y1 = v3 * ga.cscale;
                if (ga.mode == 1) {
                    int p = (col & 127) >> 1;
                    float c0v = ga.fc[r0_ * 64 + p], s0v = ga.fs[r0_ * 64 + p];
                    float c1v = ga.fc[r1_ * 64 + p], s1v = ga.fs[r1_ * 64 + p];
                    float nx0 = (x0 * c0v - y0 * s0v) * ga.oscale;
                    float ny0 = (x0 * s0v + y0 * c0v) * ga.oscale;
                    float nx1 = (x1 * c1v - y1 * s1v) * ga.oscale;
                    float ny1 = (x1 * s1v + y1 * c1v) * ga.oscale;
                    x0 = nx0; y0 = ny0; x1 = nx1; y1 = ny1;
                }
                uint32_t h0 = pack_h2f(x0, y0), l0 = pack_resid(h0, x0, y0);
                uint32_t h1 = pack_h2f(x1, y1), l1 = pack_resid(h1, x1, y1);
                *(uint32_t*)(ga.Ch + (size_t)r0_ * N + col) = h0;
                *(uint32_t*)(ga.Cl + (size_t)r0_ * N + col) = l0;
                *(uint32_t*)(ga.Ch + (size_t)r1_ * N + col) = h1;
                *(uint32_t*)(ga.Cl + (size_t)r1_ * N + col) = l1;
            }
        }
}

// Fused QKV projection (512 threads)
__global__ void __launch_bounds__(512, 1)
qkv_gemm(const __half* __restrict__ xh, const __half* __restrict__ xl,
         const float* __restrict__ fc, const float* __restrict__ fs,
         const __half* __restrict__ wq, const __half* __restrict__ wk,
         const __half* __restrict__ wv,
         __half* __restrict__ qh, __half* __restrict__ ql,
         __half* __restrict__ kh, __half* __restrict__ kl,
         __half* __restrict__ vh, __half* __restrict__ vl) {
    extern __shared__ char smem[];
    const int bx = blockIdx.x;
    GemmArgs ga;
    ga.Ah = xh; ga.Al = xl;
    ga.fc = fc; ga.fs = fs;
    ga.Cf = nullptr;
    ga.cscale = INV_WSCALE;
    int n0;
    if (bx < 32) {
        ga.B = wq; ga.Ch = qh; ga.Cl = ql;
        ga.N = D_MODEL; ga.mode = 1; ga.oscale = QK_SCALE;
        n0 = bx * 128;
    } else if (bx < 40) {
        ga.B = wk; ga.Ch = kh; ga.Cl = kl;
        ga.N = KVDIM; ga.mode = 1; ga.oscale = 1.0f;
        n0 = (bx - 32) * 128;
    } else {
        ga.B = wv; ga.Ch = vh; ga.Cl = vl;
        ga.N = KVDIM; ga.mode = 2; ga.oscale = 1.0f;
        n0 = (bx - 40) * 128;
    }
    gemm_body(ga, blockIdx.y * 128, n0, D_MODEL, smem);
}

__global__ void __launch_bounds__(512, 1)
wo_gemm(const __half* __restrict__ aoh, const __half* __restrict__ aol,
        const __half* __restrict__ wo, float* __restrict__ out) {
    extern __shared__ char smem[];
    GemmArgs ga;
    ga.Ah = aoh; ga.Al = aol; ga.B = wo;
    ga.Cf = out; ga.Ch = nullptr; ga.Cl = nullptr;
    ga.fc = nullptr; ga.fs = nullptr;
    ga.N = D_MODEL; ga.cscale = INV_WSCALE; ga.oscale = 1.0f; ga.mode = 0;
    gemm_body(ga, blockIdx.y * 128, blockIdx.x * 128, D_MODEL, smem);
}

// ---------------------------------------------------------------------------
// Conversions
// ---------------------------------------------------------------------------
__global__ void split_kernel(const float* __restrict__ in,
                             __half* __restrict__ hi, __half* __restrict__ lo,
                             int n) {
    int i = blockIdx.x * blockDim.x + threadIdx.x;
    if (i >= n) return;
    float v = in[i];
    __half h = __float2half_rn(v);
    hi[i] = h;
    lo[i] = __float2half_rn(v - __half2float(h));
}

// All 4 weight transposes (single fp16 limb, x64 scale) in one launch.
__global__ void __launch_bounds__(256) transpose_half_all(
    const float* __restrict__ wq, const float* __restrict__ wk,
    const float* __restrict__ wv, const float* __restrict__ wo,
    __half* __restrict__ oq, __half* __restrict__ ok,
    __half* __restrict__ ov, __half* __restrict__ oo) {
    const int z = blockIdx.z;
    const float* W;
    __half* o;
    int N;
    if (z == 0)      { W = wq; o = oq; N = D_MODEL; }
    else if (z == 1) { W = wk; o = ok; N = KVDIM; }
    else if (z == 2) { W = wv; o = ov; N = KVDIM; }
    else             { W = wo; o = oo; N = D_MODEL; }
    const int n0 = blockIdx.x * 32;
    if (n0 >= N) return;
    const int k0 = blockIdx.y * 32;
    const int K = D_MODEL;

    __shared__ float t[32][33];
    const int tx = threadIdx.x;
#pragma unroll
    for (int j = threadIdx.y; j < 32; j += 8)
        t[j][tx] = W[(size_t)(k0 + j) * N + n0 + tx];
    __syncthreads();
#pragma unroll
    for (int j = threadIdx.y; j < 32; j += 8)
        o[(size_t)(n0 + j) * K + k0 + tx] = __float2half_rn(t[tx][j] * WSCALE);
}

// ---------------------------------------------------------------------------
// HMMA flash attention (3-pass hi/lo splits), unchanged from R9.
// ---------------------------------------------------------------------------
#define FRSB 272
#define FQ_BYTES (128 * FRSB)
#define FKV_TILE (64 * FRSB)
#define FSTAGE (4 * FKV_TILE)
#define FSMEM (2 * FQ_BYTES + 2 * FSTAGE)

__global__ void __launch_bounds__(256, 1)
flash_hmma(const __half* __restrict__ Qh, const __half* __restrict__ Ql,
           const __half* __restrict__ Kh, const __half* __restrict__ Kl,
           const __half* __restrict__ Vh, const __half* __restrict__ Vl,
           __half* __restrict__ Oh, __half* __restrict__ Ol) {
    extern __shared__ char smf[];
    const uint32_t sb = smem_u32(smf);
    const int tid = threadIdx.x, lane = tid & 31, w = tid >> 5;
    const int head = blockIdx.y, kvh = head >> 2;
    const int qt = gridDim.x - 1 - blockIdx.x;
    const int q0 = qt * 128;
    const int nt = (q0 >> 6) + 2;

#pragma unroll
    for (int it = 0; it < 8; it++) {
        int idx = it * 256 + tid;
        int r = idx >> 4, c = idx & 15;
        size_t go = (size_t)(q0 + r) * D_MODEL + head * HEAD_DIM + c * 8;
        uint32_t so = (uint32_t)(r * FRSB + c * 16);
        CP16(sb + so, Qh + go);
        CP16(sb + FQ_BYTES + so, Ql + go);
    }

    const __half* kvsrc[4] = {Kh, Kl, Vh, Vl};
    auto issue_kv = [&](int t) {
        const int k0 = t << 6;
        const uint32_t stage = sb + 2 * FQ_BYTES + (t & 1) * FSTAGE;
#pragma unroll
        for (int it = 0; it < 16; it++) {
            int idx = it * 256 + tid;
            int op = idx >> 10;
            int r = (idx >> 4) & 63, c = idx & 15;
            const __half* g = kvsrc[op] + (size_t)(k0 + r) * KVDIM +
                              kvh * HEAD_DIM + c * 8;
            CP16(stage + op * FKV_TILE + r * FRSB + c * 16, g);
        }
        asm volatile("cp.async.commit_group;" ::: "memory");
    };
    issue_kv(0);

    const uint32_t qa_h = sb + (w * 16 + (lane & 15)) * FRSB + (lane >> 4) * 16;
    const uint32_t qa_l = qa_h + FQ_BYTES;
    const uint32_t kvoff = (uint32_t)((lane & 15) * FRSB + (lane >> 4) * 16);

    float m_lo = -1e30f, m_hi = -1e30f, l_lo = 0.f, l_hi = 0.f;
    float o_acc[16][4];
#pragma unroll
    for (int nf = 0; nf < 16; nf++)
#pragma unroll
        for (int e = 0; e < 4; e++) o_acc[nf][e] = 0.f;

    const int row_lo_g = q0 + w * 16 + (lane >> 2);
    const int row_hi_g = row_lo_g + 8;

    for (int t = 0; t < nt; t++) {
        asm volatile("cp.async.wait_group 0;" ::: "memory");
        __syncthreads();
        if (t + 1 < nt) issue_kv(t + 1);

        const uint32_t stage = sb + 2 * FQ_BYTES + (t & 1) * FSTAGE;
        const uint32_t kb = stage + kvoff;
        const uint32_t kbl = kb + FKV_TILE;
        const uint32_t vb = stage + 2 * FKV_TILE + kvoff;
        const uint32_t vbl = vb + FKV_TILE;
        const int k0 = t << 6;

        float sa32[8][4];
        uint32_t sa16[8][2];
#pragma unroll
        for (int nf = 0; nf < 8; nf++) {
#pragma unroll
            for (int e = 0; e < 4; e++) sa32[nf][e] = 0.f;
            sa16[nf][0] = 0u;
            sa16[nf][1] = 0u;
        }

#pragma unroll
        for (int ks = 0; ks < 8; ks++) {
            uint32_t ah[4], al[4];
            LDSM4(ah[0], ah[1], ah[2], ah[3], qa_h + ks * 32);
            LDSM4(al[0], al[1], al[2], al[3], qa_l + ks * 32);
#pragma unroll
            for (int ng = 0; ng < 4; ng++) {
                uint32_t h0, h1, h2, h3, l0, l1, l2, l3;
                LDSM4(h0, h1, h2, h3, kb + ng * (16 * FRSB) + ks * 32);
                LDSM4(l0, l1, l2, l3, kbl + ng * (16 * FRSB) + ks * 32);
                uint32_t bh0[2] = {h0, h2}, bh1[2] = {h1, h3};
                uint32_t bl0[2] = {l0, l2}, bl1[2] = {l1, l3};
                MMA16816(sa32[2 * ng], ah, bh0);
                MMA16816H(sa16[2 * ng], al, bh0);
                MMA16816H(sa16[2 * ng], ah, bl0);
                MMA16816(sa32[2 * ng + 1], ah, bh1);
                MMA16816H(sa16[2 * ng + 1], al, bh1);
                MMA16816H(sa16[2 * ng + 1], ah, bl1);
            }
        }

        float sa[8][4];
#pragma unroll
        for (int nf = 0; nf < 8; nf++) {
            float2 rlo = h2f2(sa16[nf][0]);
            float2 rhi = h2f2(sa16[nf][1]);
            sa[nf][0] = sa32[nf][0] + rlo.x;
            sa[nf][1] = sa32[nf][1] + rlo.y;
            sa[nf][2] = sa32[nf][2] + rhi.x;
            sa[nf][3] = sa32[nf][3] + rhi.y;
        }

        if (t >= nt - 2) {
#pragma unroll
            for (int nf = 0; nf < 8; nf++) {
                int cb = k0 + nf * 8 + (lane & 3) * 2;
                if (cb > row_lo_g) sa[nf][0] = -1e30f;
                if (cb + 1 > row_lo_g) sa[nf][1] = -1e30f;
                if (cb > row_hi_g) sa[nf][2] = -1e30f;
                if (cb + 1 > row_hi_g) sa[nf][3] = -1e30f;
            }
        }

        float tm_lo = -1e30f, tm_hi = -1e30f;
#pragma unroll
        for (int nf = 0; nf < 8; nf++) {
            tm_lo = fmaxf(tm_lo, fmaxf(sa[nf][0], sa[nf][1]));
            tm_hi = fmaxf(tm_hi, fmaxf(sa[nf][2], sa[nf][3]));
        }
        tm_lo = fmaxf(tm_lo, __shfl_xor_sync(0xffffffffu, tm_lo, 1));
        tm_lo = fmaxf(tm_lo, __shfl_xor_sync(0xffffffffu, tm_lo, 2));
        tm_hi = fmaxf(tm_hi, __shfl_xor_sync(0xffffffffu, tm_hi, 1));
        tm_hi = fmaxf(tm_hi, __shfl_xor_sync(0xffffffffu, tm_hi, 2));

        float mn_lo = fmaxf(m_lo, tm_lo), mn_hi = fmaxf(m_hi, tm_hi);
        float al_lo = __expf(m_lo - mn_lo), al_hi = __expf(m_hi - mn_hi);
        m_lo = mn_lo; m_hi = mn_hi;

        float sum_lo = 0.f, sum_hi = 0.f;
#pragma unroll
        for (int nf = 0; nf < 8; nf++) {
            sa[nf][0] = __expf(sa[nf][0] - mn_lo);
            sa[nf][1] = __expf(sa[nf][1] - mn_lo);
            sa[nf][2] = __expf(sa[nf][2] - mn_hi);
            sa[nf][3] = __expf(sa[nf][3] - mn_hi);
            sum_lo += sa[nf][0] + sa[nf][1];
            sum_hi += sa[nf][2] + sa[nf][3];
        }
        sum_lo += __shfl_xor_sync(0xffffffffu, sum_lo, 1);
        sum_lo += __shfl_xor_sync(0xffffffffu, sum_lo, 2);
        sum_hi += __shfl_xor_sync(0xffffffffu, sum_hi, 1);
        sum_hi += __shfl_xor_sync(0xffffffffu, sum_hi, 2);
        l_lo = l_lo * al_lo + sum_lo;
        l_hi = l_hi * al_hi + sum_hi;

#pragma unroll
        for (int nf = 0; nf < 16; nf++) {
            o_acc[nf][0] *= al_lo; o_acc[nf][1] *= al_lo;
            o_acc[nf][2] *= al_hi; o_acc[nf][3] *= al_hi;
        }

        uint32_t pah[4][4], pal[4][4];
#pragma unroll
        for (int j = 0; j < 4; j++) {
            pah[j][0] = pack_h2f(sa[2 * j][0], sa[2 * j][1]);
            pal[j][0] = pack_resid(pah[j][0], sa[2 * j][0], sa[2 * j][1]);
            pah[j][1] = pack_h2f(sa[2 * j][2], sa[2 * j][3]);
            pal[j][1] = pack_resid(pah[j][1], sa[2 * j][2], sa[2 * j][3]);
            pah[j][2] = pack_h2f(sa[2 * j + 1][0], sa[2 * j + 1][1]);
            pal[j][2] = pack_resid(pah[j][2], sa[2 * j + 1][0], sa[2 * j + 1][1]);
            pah[j][3] = pack_h2f(sa[2 * j + 1][2], sa[2 * j + 1][3]);
            pal[j][3] = pack_resid(pah[j][3], sa[2 * j + 1][2], sa[2 * j + 1][3]);
        }

        uint32_t o16[16][2];
#pragma unroll
        for (int nf = 0; nf < 16; nf++) { o16[nf][0] = 0u; o16[nf][1] = 0u; }

#pragma unroll
        for (int j = 0; j < 4; j++) {
#pragma unroll
            for (int dg = 0; dg < 8; dg++) {
                uint32_t h0, h1, h2, h3, l0, l1, l2, l3;
                LDSM4T(h0, h1, h2, h3, vb + j * (16 * FRSB) + dg * 32);
                LDSM4T(l0, l1, l2, l3, vbl + j * (16 * FRSB) + dg * 32);
                uint32_t bh0[2] = {h0, h1}, bh1[2] = {h2, h3};
                uint32_t bl0[2] = {l0, l1}, bl1[2] = {l2, l3};
                MMA16816(o_acc[2 * dg], pah[j], bh0);
                MMA16816H(o16[2 * dg], pal[j], bh0);
                MMA16816H(o16[2 * dg], pah[j], bl0);
                MMA16816(o_acc[2 * dg + 1], pah[j], bh1);
                MMA16816H(o16[2 * dg + 1], pal[j], bh1);
                MMA16816H(o16[2 * dg + 1], pah[j], bl1);
            }
        }
#pragma unroll
        for (int nf = 0; nf < 16; nf++) {
            float2 rlo = h2f2(o16[nf][0]);
            float2 rhi = h2f2(o16[nf][1]);
            o_acc[nf][0] += rlo.x;
            o_acc[nf][1] += rlo.y;
            o_acc[nf][2] += rhi.x;
            o_acc[nf][3] += rhi.y;
        }
    }

    const float inv_lo = 1.f / l_lo, inv_hi = 1.f / l_hi;
#pragma unroll
    for (int nf = 0; nf < 16; nf++) {
        int col = head * HEAD_DIM + nf * 8 + (lane & 3) * 2;
        float o0 = o_acc[nf][0] * inv_lo, o1 = o_acc[nf][1] * inv_lo;
        float o2 = o_acc[nf][2] * inv_hi, o3 = o_acc[nf][3] * inv_hi;
        uint32_t h0 = pack_h2f(o0, o1), L0 = pack_resid(h0, o0, o1);
        uint32_t h1 = pack_h2f(o2, o3), L1 = pack_resid(h1, o2, o3);
        *(uint32_t*)(Oh + (size_t)row_lo_g * D_MODEL + col) = h0;
        *(uint32_t*)(Ol + (size_t)row_lo_g * D_MODEL + col) = L0;
        *(uint32_t*)(Oh + (size_t)row_hi_g * D_MODEL + col) = h1;
        *(uint32_t*)(Ol + (size_t)row_hi_g * D_MODEL + col) = L1;
    }
}

// ---------------------------------------------------------------------------
// Launch
// ---------------------------------------------------------------------------
extern "C" void kernel_launch(void* const* d_in, const int* in_sizes, int n_in,
                              void* d_out, int out_size) {
    const float* x  = (const float*)d_in[0];
    const float* fc = (const float*)d_in[1];
    const float* fs = (const float*)d_in[2];
    const float* wq = (const float*)d_in[4];
    const float* wk = (const float*)d_in[5];
    const float* wv = (const float*)d_in[6];
    const float* wo = (const float*)d_in[7];
    float* out = (float*)d_out;

    __half *xh, *xl, *qh, *ql, *kh, *kl, *vh, *vl, *aoh, *aol;
    __half *pwq, *pwk, *pwv, *pwo;
    cudaGetSymbolAddress((void**)&xh,  g_xh);
    cudaGetSymbolAddress((void**)&xl,  g_xl);
    cudaGetSymbolAddress((void**)&qh,  g_qh);
    cudaGetSymbolAddress((void**)&ql,  g_ql);
    cudaGetSymbolAddress((void**)&kh,  g_kh);
    cudaGetSymbolAddress((void**)&kl,  g_kl);
    cudaGetSymbolAddress((void**)&vh,  g_vh);
    cudaGetSymbolAddress((void**)&vl,  g_vl);
    cudaGetSymbolAddress((void**)&aoh, g_aoh);
    cudaGetSymbolAddress((void**)&aol, g_aol);
    cudaGetSymbolAddress((void**)&pwq, g_wq);
    cudaGetSymbolAddress((void**)&pwk, g_wk);
    cudaGetSymbolAddress((void**)&pwv, g_wv);
    cudaGetSymbolAddress((void**)&pwo, g_wo);

    cudaFuncSetAttribute(qkv_gemm, cudaFuncAttributeMaxDynamicSharedMemorySize, G_SMEM);
    cudaFuncSetAttribute(wo_gemm,  cudaFuncAttributeMaxDynamicSharedMemorySize, G_SMEM);
    cudaFuncSetAttribute(flash_hmma, cudaFuncAttributeMaxDynamicSharedMemorySize, FSMEM);

    split_kernel<<<(S_LEN * D_MODEL + 255) / 256, 256>>>(x, xh, xl, S_LEN * D_MODEL);
    transpose_half_all<<<dim3(D_MODEL / 32, D_MODEL / 32, 4), dim3(32, 8)>>>(
        wq, wk, wv, wo, pwq, pwk, pwv, pwo);

    qkv_gemm<<<dim3(48, S_LEN / 128), 512, G_SMEM>>>(
        xh, xl, fc, fs, pwq, pwk, pwv,
        qh, ql, kh, kl, vh, vl);

    flash_hmma<<<dim3(S_LEN / 128, N_HEADS), 256, FSMEM>>>(
        qh, ql, kh, kl, vh, vl, aoh, aol);

    wo_gemm<<<dim3(D_MODEL / 128, S_LEN / 128), 512, G_SMEM>>>(
        aoh, aol, pwo, out);
}